// round 15
// baseline (speedup 1.0000x reference)
#include <cuda_runtime.h>
#include <cstdint>

// Problem constants (reference: N_NODES=100000, N_EDGES=2000000, DIM=64)
#define MAX_NODES 100000
#define MAX_EDGES 2000000
#define DIM 64

// Scratch (device globals — no allocation allowed)
__device__ float g_agg[MAX_NODES * DIM];     // 25.6 MB
__device__ float g_h1 [MAX_NODES * DIM];     // 25.6 MB
__device__ int   g_cnt [MAX_NODES];
__device__ int   g_scan[MAX_NODES];
__device__ int   g_part[256];
__device__ int   g_rowptr[MAX_NODES + 1];
__device__ int   g_pos [MAX_NODES];
__device__ int   g_csr [MAX_EDGES];

// ===========================================================================
// CSR build
// ===========================================================================
__global__ void zero_cnt_kernel(int n) {
    int i = blockIdx.x * blockDim.x + threadIdx.x;
    if (i < n) g_cnt[i] = 0;
}

__global__ void deg_count_kernel(const int* __restrict__ dst, int E) {
    int e = blockIdx.x * blockDim.x + threadIdx.x;
    if (e < E) atomicAdd(&g_cnt[dst[e]], 1);
}

__global__ __launch_bounds__(1024) void scanA_kernel(int n) {
    int tid = threadIdx.x, lane = tid & 31, wid = tid >> 5;
    int i = blockIdx.x * 1024 + tid;
    int v = (i < n) ? g_cnt[i] : 0;
    int incl = v;
#pragma unroll
    for (int off = 1; off < 32; off <<= 1) {
        int t = __shfl_up_sync(0xffffffffu, incl, off);
        if (lane >= off) incl += t;
    }
    __shared__ int wsum[32];
    if (lane == 31) wsum[wid] = incl;
    __syncthreads();
    if (wid == 0) {
        int w = wsum[lane];
        int wi = w;
#pragma unroll
        for (int off = 1; off < 32; off <<= 1) {
            int t = __shfl_up_sync(0xffffffffu, wi, off);
            if (lane >= off) wi += t;
        }
        wsum[lane] = wi - w;
    }
    __syncthreads();
    int excl = incl - v + wsum[wid];
    if (i < n) g_scan[i] = excl;
    if (tid == 1023) g_part[blockIdx.x] = excl + v;
}

// parallel scan of block partials (nb <= 128)
__global__ __launch_bounds__(128) void scanB_kernel(int nb, int n, int E) {
    int tid = threadIdx.x, lane = tid & 31, wid = tid >> 5;
    int v = (tid < nb) ? g_part[tid] : 0;
    int incl = v;
#pragma unroll
    for (int off = 1; off < 32; off <<= 1) {
        int t = __shfl_up_sync(0xffffffffu, incl, off);
        if (lane >= off) incl += t;
    }
    __shared__ int wsum[4];
    if (lane == 31) wsum[wid] = incl;
    __syncthreads();
    int woff = 0;
    for (int w = 0; w < wid; w++) woff += wsum[w];
    if (tid < nb) g_part[tid] = incl - v + woff;
    if (tid == 0) g_rowptr[n] = E;
}

__global__ __launch_bounds__(1024) void scanC_kernel(int n) {
    int i = blockIdx.x * 1024 + threadIdx.x;
    if (i < n) {
        g_rowptr[i] = g_scan[i] + g_part[blockIdx.x];
        g_pos[i] = 0;
    }
}

__global__ void fill_kernel(const int* __restrict__ src,
                            const int* __restrict__ dst, int E) {
    int e = blockIdx.x * blockDim.x + threadIdx.x;
    if (e >= E) return;
    int d = dst[e];
    int p = atomicAdd(&g_pos[d], 1);
    g_csr[g_rowptr[d] + p] = src[e];
}

// ===========================================================================
// Aggregation: warp per node, 32 lanes x float2, CSR gather, no atomics.
// ===========================================================================
__global__ void agg_kernel(const float* __restrict__ h,
                           float* __restrict__ agg, int n) {
    int gw = (blockIdx.x * blockDim.x + threadIdx.x) >> 5;
    if (gw >= n) return;
    int lane = threadIdx.x & 31;
    int s0 = g_rowptr[gw], s1 = g_rowptr[gw + 1];
    float ax = 0.f, ay = 0.f;
    for (int base = s0; base < s1; base += 32) {
        int idx = 0;
        if (base + lane < s1) idx = g_csr[base + lane];
        int m = min(32, s1 - base);
        for (int j = 0; j < m; j++) {
            int s = __shfl_sync(0xffffffffu, idx, j);
            float2 v = *reinterpret_cast<const float2*>(h + s * DIM + lane * 2);
            ax += v.x; ay += v.y;
        }
    }
    float inv = 1.f / fmaxf((float)(s1 - s0), 1.f);
    float2 r; r.x = ax * inv; r.y = ay * inv;
    *reinterpret_cast<float2*>(agg + gw * DIM + lane * 2) = r;
}

// ===========================================================================
// Linear v3 (packed f32x2): out = act( concat(h, agg) @ W + b )
// Block = 128 threads, tile = 128 nodes x 64 cols.
// Thread tile = 8 nodes x 8 cols = 32 packed f32x2 accumulators (col pairs:
// W[k][c], W[k][c+1] contiguous in sW -> natural b-operand; only the h
// broadcast needs a mov.b64 {h,h} pack, on the ALU pipe).
// Per k-quad: 16 LDS.128 + 32 MOV + 128 FFMA2 for 256 FMAs (1 B LDS / FMA).
// ===========================================================================
#define SROW_STRIDE 132
#define SMEM_FLOATS (8192 + 64 + 128 * SROW_STRIDE)

#define FMA_F32X2(d, a, b, c) \
    asm("fma.rn.f32x2 %0, %1, %2, %3;" : "=l"(d) : "l"(a), "l"(b), "l"(c))
#define PACK_F32X2(out, lo, hi) \
    asm("mov.b64 %0, {%1, %2};" : "=l"(out) : "f"(lo), "f"(hi))
#define UNPACK_F32X2(lo, hi, in) \
    asm("mov.b64 {%0, %1}, %2;" : "=f"(lo), "=f"(hi) : "l"(in))

__global__ __launch_bounds__(128) void linear_kernel(
        const float* __restrict__ h,
        const float* __restrict__ agg,
        const float* __restrict__ W,
        const float* __restrict__ b,
        float* __restrict__ out,
        int n, int relu) {
    extern __shared__ float smem[];
    float* sW   = smem;                 // [128][64]
    float* sb   = smem + 8192;          // [64]
    float* srow = smem + 8192 + 64;     // [128][SROW_STRIDE]

    int tid = threadIdx.x;

    for (int i = tid; i < 2 * DIM * DIM; i += 128) sW[i] = W[i];
    if (tid < DIM) sb[tid] = b[tid];
    __syncthreads();

    int cg = tid & 7;         // col group: cols cg*8 .. cg*8+7
    int ng = tid >> 3;        // node group: nodes ng*8 .. ng*8+7 (16 groups)
    int c0 = cg << 3;
    int nb = ng << 3;

    int ntiles = (n + 127) >> 7;
    for (int tile = blockIdx.x; tile < ntiles; tile += gridDim.x) {
        int base = tile << 7;

        // ---- stage srow: [128 nodes][128] = concat(h, agg) ----
        // 4096 float4; 32 per thread
#pragma unroll
        for (int it = 0; it < 32; it++) {
            int idx = it * 128 + tid;
            int row = idx >> 5;
            int q   = idx & 31;
            int node = base + row;
            if (node < n) {
                float4 v;
                if (q < 16)
                    v = *reinterpret_cast<const float4*>(h + node * DIM + (q << 2));
                else
                    v = *reinterpret_cast<const float4*>(agg + node * DIM + ((q - 16) << 2));
                *reinterpret_cast<float4*>(&srow[row * SROW_STRIDE + (q << 2)]) = v;
            }
        }
        __syncthreads();

        // ---- init accumulators from bias (packed col pairs) ----
        unsigned long long acc[8][4];
        {
            ulonglong2 b01 = *reinterpret_cast<const ulonglong2*>(&sb[c0]);
            ulonglong2 b23 = *reinterpret_cast<const ulonglong2*>(&sb[c0 + 4]);
#pragma unroll
            for (int i = 0; i < 8; i++) {
                acc[i][0] = b01.x; acc[i][1] = b01.y;
                acc[i][2] = b23.x; acc[i][3] = b23.y;
            }
        }

        // ---- main loop ----
#pragma unroll 4
        for (int k = 0; k < 2 * DIM; k += 4) {
            float4 hv[8];
#pragma unroll
            for (int i = 0; i < 8; i++)
                hv[i] = *reinterpret_cast<const float4*>(&srow[(nb + i) * SROW_STRIDE + k]);
#pragma unroll
            for (int kk = 0; kk < 4; kk++) {
                ulonglong2 w01 = *reinterpret_cast<const ulonglong2*>(&sW[(k + kk) * DIM + c0]);
                ulonglong2 w23 = *reinterpret_cast<const ulonglong2*>(&sW[(k + kk) * DIM + c0 + 4]);
#pragma unroll
                for (int i = 0; i < 8; i++) {
                    float hs = (kk == 0) ? hv[i].x : (kk == 1) ? hv[i].y
                             : (kk == 2) ? hv[i].z : hv[i].w;
                    unsigned long long hp;
                    PACK_F32X2(hp, hs, hs);
                    FMA_F32X2(acc[i][0], hp, w01.x, acc[i][0]);
                    FMA_F32X2(acc[i][1], hp, w01.y, acc[i][1]);
                    FMA_F32X2(acc[i][2], hp, w23.x, acc[i][2]);
                    FMA_F32X2(acc[i][3], hp, w23.y, acc[i][3]);
                }
            }
        }

        // ---- epilogue ----
#pragma unroll
        for (int i = 0; i < 8; i++) {
            int node = base + nb + i;
            if (node < n) {
                float4 r0, r1;
                UNPACK_F32X2(r0.x, r0.y, acc[i][0]);
                UNPACK_F32X2(r0.z, r0.w, acc[i][1]);
                UNPACK_F32X2(r1.x, r1.y, acc[i][2]);
                UNPACK_F32X2(r1.z, r1.w, acc[i][3]);
                if (relu) {
                    r0.x = fmaxf(r0.x, 0.f); r0.y = fmaxf(r0.y, 0.f);
                    r0.z = fmaxf(r0.z, 0.f); r0.w = fmaxf(r0.w, 0.f);
                    r1.x = fmaxf(r1.x, 0.f); r1.y = fmaxf(r1.y, 0.f);
                    r1.z = fmaxf(r1.z, 0.f); r1.w = fmaxf(r1.w, 0.f);
                }
                *reinterpret_cast<float4*>(out + node * DIM + c0)     = r0;
                *reinterpret_cast<float4*>(out + node * DIM + c0 + 4) = r1;
            }
        }
        __syncthreads();   // srow reuse guard for next tile
    }
}

// ===========================================================================
// Launch
// Inputs: x[100000*64] f32, edge_index[2*2000000] i32,
//         W0[128*64] f32, b0[64] f32, W1[128*64] f32, b1[64] f32
// Output: [100000*64] f32
// ===========================================================================
extern "C" void kernel_launch(void* const* d_in, const int* in_sizes, int n_in,
                              void* d_out, int out_size) {
    const float* x  = (const float*)d_in[0];
    const int*   ei = (const int*)  d_in[1];
    const float* W0 = (const float*)d_in[2];
    const float* b0 = (const float*)d_in[3];
    const float* W1 = (const float*)d_in[4];
    const float* b1 = (const float*)d_in[5];
    float* out = (float*)d_out;

    int n = in_sizes[0] / DIM;          // 100000
    int E = in_sizes[1] / 2;            // 2000000
    const int* src = ei;
    const int* dst = ei + E;

    float* agg;  cudaGetSymbolAddress((void**)&agg, g_agg);
    float* h1;   cudaGetSymbolAddress((void**)&h1,  g_h1);

    static int smem_set = 0;
    size_t smem_bytes = SMEM_FLOATS * sizeof(float);   // 100608 B
    if (!smem_set) {
        cudaFuncSetAttribute(linear_kernel,
                             cudaFuncAttributeMaxDynamicSharedMemorySize,
                             (int)smem_bytes);
        smem_set = 1;
    }

    int nb = (n + 1023) / 1024;               // 98 scan blocks

    // ---- CSR build (once; reused by both layers) ----
    zero_cnt_kernel<<<(n + 255) / 256, 256>>>(n);
    deg_count_kernel<<<(E + 255) / 256, 256>>>(dst, E);
    scanA_kernel<<<nb, 1024>>>(n);
    scanB_kernel<<<1, 128>>>(nb, n, E);
    scanC_kernel<<<nb, 1024>>>(n);
    fill_kernel<<<(E + 255) / 256, 256>>>(src, dst, E);

    int agg_blocks = (int)(((long long)n * 32 + 255) / 256);

    // ---- layer 0 ----
    agg_kernel<<<agg_blocks, 256>>>(x, agg, n);
    linear_kernel<<<296, 128, smem_bytes>>>(x, agg, W0, b0, h1, n, /*relu=*/1);

    // ---- layer 1 ----
    agg_kernel<<<agg_blocks, 256>>>(h1, agg, n);
    linear_kernel<<<296, 128, smem_bytes>>>(h1, agg, W1, b1, out, n, /*relu=*/0);
}